// round 1
// baseline (speedup 1.0000x reference)
#include <cuda_runtime.h>
#include <cstdint>
#include <climits>

#define MAXN 20000
#define DEG  32
#define MAXE (MAXN * DEG)
#define GB   64
#define TB   512
#define NW   (TB / 32)

// ---------------- device state (no dynamic allocation allowed) ----------------
__device__ int    d_nbr[MAXE];        // per-node sorted neighbor (dst) list
__device__ int    d_eidx[MAXE];       // original edge index of sorted edge
__device__ int    d_visited[MAXN];
__device__ int    d_cand[MAXN];       // per-node candidate slot key (atomicMin)
__device__ float4 d_quat[MAXN];       // node quaternions (w,x,y,z)
__device__ int    d_frontier[2][MAXN];
__device__ int    d_cnt[2];
__device__ int    d_btot[GB];
__device__ unsigned d_barCount;
__device__ unsigned d_barGen;

// ---------------- per-node sort of 32 edges by (err, idx) ----------------
__global__ void sort_kernel(const float* __restrict__ ea,
                            const int* __restrict__ ei, int N, int E) {
    int w    = (blockIdx.x * blockDim.x + threadIdx.x) >> 5;
    int lane = threadIdx.x & 31;
    if (w >= N) return;
    int e = w * DEG + lane;

    float qw  = ea[4 * e];                               // quaternion w component
    float aw  = fminf(fabsf(qw), 1.0f);
    float err = 2.0f * (acosf(aw) * 57.29577951308232f); // matches 2*degrees(arccos)
    int   idx = lane;                                    // original within-node index
    int   v   = ei[E + e];                               // dst

    // bitonic sort ascending by compound key (err, idx) — keys all distinct
    #pragma unroll
    for (int k = 2; k <= 32; k <<= 1) {
        #pragma unroll
        for (int j = k >> 1; j > 0; j >>= 1) {
            float oerr = __shfl_xor_sync(0xffffffffu, err, j);
            int   oidx = __shfl_xor_sync(0xffffffffu, idx, j);
            int   ov   = __shfl_xor_sync(0xffffffffu, v,   j);
            bool asc    = ((lane & k) == 0);
            bool lower  = ((lane & j) == 0);
            bool oSmall = (oerr < err) || (oerr == err && oidx < idx);
            bool take   = asc ? (lower ? oSmall : !oSmall)
                              : (lower ? !oSmall : oSmall);
            if (take) { err = oerr; idx = oidx; v = ov; }
        }
    }
    d_nbr[w * DEG + lane]  = v;
    d_eidx[w * DEG + lane] = w * DEG + idx;
}

// ---------------- per-launch state reset (determinism under graph replay) ----
__global__ void init_kernel(const int* __restrict__ start,
                            float* __restrict__ out, int N, int off) {
    int i = blockIdx.x * blockDim.x + threadIdx.x;
    int s = start[0];
    if (i < N) {
        d_visited[i] = (i == s) ? 1 : 0;
        d_cand[i]    = INT_MAX;
        d_quat[i]    = make_float4(1.0f, 0.0f, 0.0f, 0.0f);
    }
    if (i == 0) {
        d_frontier[0][0] = s;
        d_cnt[0] = 1;
        d_cnt[1] = 0;
        d_barCount = 0;
        d_barGen   = 0;
    }
    if (i < off) out[i] = (float)s;  // leading scalar output (start_node)
}

// ---------------- software grid barrier (GB co-resident blocks) --------------
__device__ __forceinline__ void grid_barrier() {
    __threadfence();       // publish writes; gpu-scope fence also invalidates L1D
    __syncthreads();
    if (threadIdx.x == 0) {
        volatile unsigned* gen = &d_barGen;
        unsigned g = *gen;
        __threadfence();
        if (atomicAdd(&d_barCount, 1u) == (unsigned)(GB - 1)) {
            d_barCount = 0;
            __threadfence();
            *gen = g + 1;
        } else {
            while (*gen == g) { }
        }
    }
    __syncthreads();
}

// ---------------- persistent level-synchronous BFS ---------------------------
__global__ void __launch_bounds__(TB) bfs_kernel(const float* __restrict__ ea, int N) {
    const int tid  = threadIdx.x;
    const int lane = tid & 31;
    const int wid  = tid >> 5;
    const int gtid = blockIdx.x * TB + tid;
    const int TT   = GB * TB;
    __shared__ int sh_warp[NW];
    __shared__ int sh_off;

    int cur = 0;
    for (int lvl = 0; lvl <= N; ++lvl) {
        int fcnt = __ldcg(&d_cnt[cur]);
        if (fcnt <= 0) break;
        int nxt = cur ^ 1;
        int S   = fcnt * DEG;

        // Phase 1: propose — unique slot key s = u_rank*32 + idx
        for (int s = gtid; s < S; s += TT) {
            int u = __ldcg(&d_frontier[cur][s >> 5]);
            int v = d_nbr[u * DEG + (s & 31)];
            if (__ldcg(&d_visited[v]) == 0) atomicMin(&d_cand[v], s);
        }
        grid_barrier();

        // contiguous chunk per block (preserves slot order for ranking)
        int C    = (S + GB - 1) / GB;
        int base = blockIdx.x * C;
        int end  = min(base + C, S);
        int nIt  = (C + TB - 1) / TB;

        // Phase 2: count winners in my chunk
        int cntW = 0;
        for (int it = 0; it < nIt; ++it) {
            int s = base + it * TB + tid;
            if (s < end) {
                int u = __ldcg(&d_frontier[cur][s >> 5]);
                int v = d_nbr[u * DEG + (s & 31)];
                if (__ldcg(&d_visited[v]) == 0 && __ldcg(&d_cand[v]) == s) cntW++;
            }
        }
        #pragma unroll
        for (int o = 16; o > 0; o >>= 1) cntW += __shfl_xor_sync(0xffffffffu, cntW, o);
        if (lane == 0) sh_warp[wid] = cntW;
        __syncthreads();
        if (tid == 0) {
            int t = 0;
            for (int w2 = 0; w2 < NW; ++w2) t += sh_warp[w2];
            d_btot[blockIdx.x] = t;
        }
        grid_barrier();

        // Phase 3: exclusive block offsets, then in-order finalize
        if (tid == 0) {
            int off = 0;
            for (int b = 0; b < (int)blockIdx.x; ++b) off += __ldcg(&d_btot[b]);
            sh_off = off;
            if (blockIdx.x == 0) {
                int tot = 0;
                for (int b = 0; b < GB; ++b) tot += __ldcg(&d_btot[b]);
                d_cnt[nxt] = tot;
            }
        }
        __syncthreads();

        int running = sh_off;
        for (int it = 0; it < nIt; ++it) {
            int s = base + it * TB + tid;
            bool win = false;
            int u = 0, v = 0;
            if (s < end) {
                u   = __ldcg(&d_frontier[cur][s >> 5]);
                v   = d_nbr[u * DEG + (s & 31)];
                win = (__ldcg(&d_visited[v]) == 0) && (__ldcg(&d_cand[v]) == s);
            }
            unsigned m = __ballot_sync(0xffffffffu, win);
            if (lane == 0) sh_warp[wid] = __popc(m);
            __syncthreads();
            int woff = 0, tot = 0;
            for (int w2 = 0; w2 < NW; ++w2) {
                int c = sh_warp[w2];
                if (w2 < wid) woff += c;
                tot += c;
            }
            if (win) {
                int rank = running + woff + __popc(m & ((1u << lane) - 1u));
                int eidx = d_eidx[u * DEG + (s & 31)];
                // edge quaternion (w,x,y,z); inverse = conjugate
                const float4 q = *reinterpret_cast<const float4*>(ea + 4 * eidx);
                float4 b = __ldcg(&d_quat[u]);  // (w,x,y,z) in .x..w
                float aw = q.x, ax = -q.y, ay = -q.z, az = -q.w;
                float4 r;
                r.x = aw * b.x - ax * b.y - ay * b.z - az * b.w; // w
                r.y = aw * b.y + ax * b.x + ay * b.w - az * b.z; // x
                r.z = aw * b.z - ax * b.w + ay * b.x + az * b.y; // y
                r.w = aw * b.w + ax * b.z - ay * b.y + az * b.x; // z
                d_quat[v] = r;
                d_visited[v] = 1;
                d_frontier[nxt][rank] = v;
            }
            __syncthreads();
            running += tot;
        }
        grid_barrier();
        cur = nxt;
    }
}

// ---------------- write output -----------------------------------------------
__global__ void copy_kernel(float* __restrict__ out, int off, int N, int out_size) {
    int i = blockIdx.x * blockDim.x + threadIdx.x;
    int M = 4 * N;
    if (i < M && off + i < out_size) {
        out[off + i] = reinterpret_cast<const float*>(d_quat)[i];
    }
}

// ---------------- launch ------------------------------------------------------
extern "C" void kernel_launch(void* const* d_in, const int* in_sizes, int n_in,
                              void* d_out, int out_size) {
    const float* ea    = (const float*)d_in[0];  // edge_attr [E,4] f32
    const int*   ei    = (const int*)d_in[1];    // edge_index [2,E] i32
    const int*   start = (const int*)d_in[2];    // start_node scalar i32

    int E = in_sizes[0] / 4;
    int N = E / DEG;
    float* out = (float*)d_out;
    int off = out_size - 4 * N;
    if (off < 0) off = 0;

    int t = 256;
    int initN = (N > off) ? N : off;
    sort_kernel<<<(N * DEG + t - 1) / t, t>>>(ea, ei, N, E);
    init_kernel<<<(initN + t - 1) / t, t>>>(start, out, N, off);
    bfs_kernel<<<GB, TB>>>(ea, N);
    copy_kernel<<<(4 * N + t - 1) / t, t>>>(out, off, N, out_size);
}

// round 2
// speedup vs baseline: 2.0458x; 2.0458x over previous
#include <cuda_runtime.h>
#include <cstdint>

#define MAXN 20000
#define DEG  32
#define MAXE (MAXN * DEG)
#define GB   148
#define TB   1024

typedef unsigned long long u64;

// ---------------- device state (no dynamic allocation allowed) ----------------
__device__ int    d_nbr[MAXE];        // per-node sorted neighbor (dst) list
__device__ int    d_eidx[MAXE];       // original edge index of sorted edge
__device__ u64    d_key[MAXN];        // path-lex key; ULLONG_MAX = unreached
__device__ float4 d_quat[MAXN];       // node quaternions (w,x,y,z)
__device__ int    d_frontier[2][MAXN];
__device__ int    d_cnt[2];
__device__ unsigned d_barCount;
__device__ unsigned d_barGen;

// ---------------- per-node sort of 32 edges by (err, idx) ----------------
__global__ void sort_kernel(const float* __restrict__ ea,
                            const int* __restrict__ ei, int N, int E) {
    int w    = (blockIdx.x * blockDim.x + threadIdx.x) >> 5;
    int lane = threadIdx.x & 31;
    if (w >= N) return;
    int e = w * DEG + lane;

    float qw  = ea[4 * e];                               // quaternion w component
    float aw  = fminf(fabsf(qw), 1.0f);
    float err = 2.0f * (acosf(aw) * 57.29577951308232f); // matches 2*degrees(arccos)
    int   idx = lane;                                    // original within-node index
    int   v   = ei[E + e];                               // dst

    // bitonic sort ascending by compound key (err, idx) — keys all distinct
    #pragma unroll
    for (int k = 2; k <= 32; k <<= 1) {
        #pragma unroll
        for (int j = k >> 1; j > 0; j >>= 1) {
            float oerr = __shfl_xor_sync(0xffffffffu, err, j);
            int   oidx = __shfl_xor_sync(0xffffffffu, idx, j);
            int   ov   = __shfl_xor_sync(0xffffffffu, v,   j);
            bool asc    = ((lane & k) == 0);
            bool lower  = ((lane & j) == 0);
            bool oSmall = (oerr < err) || (oerr == err && oidx < idx);
            bool take   = asc ? (lower ? oSmall : !oSmall)
                              : (lower ? !oSmall : oSmall);
            if (take) { err = oerr; idx = oidx; v = ov; }
        }
    }
    d_nbr[w * DEG + lane]  = v;
    d_eidx[w * DEG + lane] = w * DEG + idx;
}

// ---------------- per-launch state reset (determinism under graph replay) ----
__global__ void init_kernel(const int* __restrict__ start,
                            float* __restrict__ out, int N, int off) {
    int i = blockIdx.x * blockDim.x + threadIdx.x;
    int s = start[0];
    if (i < N) {
        d_key[i]  = (i == s) ? 1ull : ~0ull;   // start key = 1 (level-0 sentinel)
        d_quat[i] = make_float4(1.0f, 0.0f, 0.0f, 0.0f);
        // full output init: identity quats; winners overwritten by bfs_kernel
        float* o = out + off + 4 * i;
        o[0] = 1.0f; o[1] = 0.0f; o[2] = 0.0f; o[3] = 0.0f;
    }
    if (i == 0) {
        d_frontier[0][0] = s;
        d_cnt[0] = 1;
        d_cnt[1] = 0;
        d_barCount = 0;
        d_barGen   = 0;
    }
    if (i < off) out[i] = (float)s;  // leading scalar output (start_node)
}

// ---------------- software grid barrier (GB co-resident blocks) --------------
__device__ __forceinline__ void grid_barrier() {
    __threadfence();       // publish writes (gpu-scope)
    __syncthreads();
    if (threadIdx.x == 0) {
        volatile unsigned* gen = &d_barGen;
        unsigned g = *gen;
        __threadfence();
        if (atomicAdd(&d_barCount, 1u) == (unsigned)(GB - 1)) {
            d_barCount = 0;
            __threadfence();
            *gen = g + 1;
        } else {
            while (*gen == g) { }
        }
    }
    __syncthreads();
}

// ---------------- persistent level-synchronous BFS ---------------------------
// Path-lex keys: key(child) = key(parent)*32 + sorted_edge_idx, key(start)=1.
// Level-L keys lie in [32^L, 32^(L+1)) => old winners always keep their key
// under atomicMin (no explicit visited flag), and atomicMin picks exactly the
// serial-BFS parent. Next-frontier order is irrelevant (keys carry ordering),
// so compaction is an unordered atomicAdd ticket.
__global__ void __launch_bounds__(TB) bfs_kernel(const float* __restrict__ ea,
                                                 float* __restrict__ out,
                                                 int off) {
    const int gtid = blockIdx.x * TB + threadIdx.x;
    const int TT   = GB * TB;

    int cur = 0;
    for (int lvl = 0; lvl < 64; ++lvl) {
        int fcnt = __ldcg(&d_cnt[cur]);
        if (fcnt <= 0) break;
        int nxt = cur ^ 1;
        int S   = fcnt * DEG;

        // Phase 1: propose (unconditional 64-bit atomicMin of path-lex key)
        for (int s = gtid; s < S; s += TT) {
            int u  = __ldcg(&d_frontier[cur][s >> 5]);
            u64 ku = __ldcg(&d_key[u]);
            int v  = d_nbr[(u << 5) + (s & 31)];
            atomicMin(&d_key[v], (ku << 5) | (u64)(s & 31));
        }
        grid_barrier();

        // Phase 2: resolve winners, unordered compaction, quat propagation
        if (gtid == 0) d_cnt[cur] = 0;   // safe: everyone read fcnt before B1
        for (int s = gtid; s < S; s += TT) {
            int u  = __ldcg(&d_frontier[cur][s >> 5]);
            u64 ku = __ldcg(&d_key[u]);
            int v  = d_nbr[(u << 5) + (s & 31)];
            u64 mk = (ku << 5) | (u64)(s & 31);
            if (__ldcg(&d_key[v]) == mk) {
                int pos = atomicAdd(&d_cnt[nxt], 1);
                d_frontier[nxt][pos] = v;
                int eidx = d_eidx[(u << 5) + (s & 31)];
                const float4 q = *reinterpret_cast<const float4*>(ea + 4 * eidx);
                float4 b = __ldcg(&d_quat[u]);  // parent quat is final (BFS level order)
                float aw = q.x, ax = -q.y, ay = -q.z, az = -q.w;  // conjugate
                float4 r;
                r.x = aw * b.x - ax * b.y - ay * b.z - az * b.w; // w
                r.y = aw * b.y + ax * b.x + ay * b.w - az * b.z; // x
                r.z = aw * b.z - ax * b.w + ay * b.x + az * b.y; // y
                r.w = aw * b.w + ax * b.z - ay * b.y + az * b.x; // z
                d_quat[v] = r;
                float* o = out + off + 4 * v;   // write result directly (no copy kernel)
                o[0] = r.x; o[1] = r.y; o[2] = r.z; o[3] = r.w;
            }
        }
        grid_barrier();
        cur = nxt;
    }
}

// ---------------- launch ------------------------------------------------------
extern "C" void kernel_launch(void* const* d_in, const int* in_sizes, int n_in,
                              void* d_out, int out_size) {
    const float* ea    = (const float*)d_in[0];  // edge_attr [E,4] f32
    const int*   ei    = (const int*)d_in[1];    // edge_index [2,E] i32
    const int*   start = (const int*)d_in[2];    // start_node scalar i32

    int E = in_sizes[0] / 4;
    int N = E / DEG;
    float* out = (float*)d_out;
    int off = out_size - 4 * N;
    if (off < 0) off = 0;

    int t = 256;
    int initN = (N > off) ? N : off;
    sort_kernel<<<(N * DEG + t - 1) / t, t>>>(ea, ei, N, E);
    init_kernel<<<(initN + t - 1) / t, t>>>(start, out, N, off);
    bfs_kernel<<<GB, TB>>>(ea, out, off);
}